// round 1
// baseline (speedup 1.0000x reference)
#include <cuda_runtime.h>
#include <cuda_bf16.h>

// Problem constants
#define BB    2
#define SS    2048
#define DM    1024
#define NH    16
#define DK    64
#define DFF   4096
#define NTOK  (BB*SS)      // 4096
#define OUT_ELEMS ((long)NTOK*DM)          // 4,194,304
#define ATTN_ELEMS ((long)BB*NH*SS*SS)     // 134,217,728

// Scratch (device globals: allocation-free per harness rules)
__device__ float g_q  [NTOK*DM];
__device__ float g_k  [NTOK*DM];
__device__ float g_v  [NTOK*DM];
__device__ float g_ctx[NTOK*DM];
__device__ float g_t0 [NTOK*DM];   // attn_out, later ffn2 out
__device__ float g_x1 [NTOK*DM];   // after LN1
__device__ float g_ff [NTOK*DFF];  // ffn hidden

// ---------------------------------------------------------------------------
// Generic register-blocked SGEMM.
//   C = alpha * A * op(B) + bias  (op = transpose if TRANSB), optional ReLU.
//   Batched via blockIdx.z with (z/16, z%16) offsets to support per-(b,h)
//   attention sub-matrices living inside [NTOK, DM] buffers.
// ---------------------------------------------------------------------------
template<int BM, int BN, int BK, int TM, int TN, bool TRANSB, bool RELU>
__global__ void __launch_bounds__((BM/TM)*(BN/TN))
gemm_k(const float* __restrict__ A, const float* __restrict__ Bm,
       const float* __restrict__ bias, float* __restrict__ C,
       int M, int N, int K, int lda, int ldb, int ldc,
       long sA_b, long sA_h, long sB_b, long sB_h, long sC_b, long sC_h,
       float alpha)
{
    constexpr int THREADS = (BM/TM)*(BN/TN);
    const int z  = blockIdx.z;
    const int zb = z >> 4, zh = z & 15;
    A  += zb*sA_b + zh*sA_h;
    Bm += zb*sB_b + zh*sB_h;
    C  += zb*sC_b + zh*sC_h;

    __shared__ float As[BK][BM];
    __shared__ float Bs[BK][BN];

    const int tid  = threadIdx.x;
    const int tcol = tid % (BN/TN);
    const int trow = tid / (BN/TN);
    const int m0 = blockIdx.y * BM;
    const int n0 = blockIdx.x * BN;

    float acc[TM][TN];
    #pragma unroll
    for (int i = 0; i < TM; i++)
        #pragma unroll
        for (int j = 0; j < TN; j++) acc[i][j] = 0.f;

    for (int k0 = 0; k0 < K; k0 += BK) {
        // --- load A tile (BM x BK), float4 along K, store transposed ---
        #pragma unroll
        for (int i = tid; i < BM*BK/4; i += THREADS) {
            int m  = i / (BK/4);
            int kk = (i % (BK/4)) * 4;
            float4 v = *(const float4*)&A[(long)(m0+m)*lda + k0 + kk];
            As[kk+0][m] = v.x; As[kk+1][m] = v.y;
            As[kk+2][m] = v.z; As[kk+3][m] = v.w;
        }
        // --- load B tile into Bs[k][n] ---
        if (!TRANSB) {
            #pragma unroll
            for (int i = tid; i < BK*BN/4; i += THREADS) {
                int kk = i / (BN/4);
                int n  = (i % (BN/4)) * 4;
                float4 v = *(const float4*)&Bm[(long)(k0+kk)*ldb + n0 + n];
                *(float4*)&Bs[kk][n] = v;
            }
        } else {
            #pragma unroll
            for (int i = tid; i < BN*BK/4; i += THREADS) {
                int n  = i / (BK/4);
                int kk = (i % (BK/4)) * 4;
                float4 v = *(const float4*)&Bm[(long)(n0+n)*ldb + k0 + kk];
                Bs[kk+0][n] = v.x; Bs[kk+1][n] = v.y;
                Bs[kk+2][n] = v.z; Bs[kk+3][n] = v.w;
            }
        }
        __syncthreads();

        #pragma unroll
        for (int kk = 0; kk < BK; kk++) {
            float ar[TM], br[TN];
            #pragma unroll
            for (int i = 0; i < TM/4; i++)
                *(float4*)&ar[i*4] = *(const float4*)&As[kk][trow*TM + i*4];
            #pragma unroll
            for (int j = 0; j < TN/4; j++)
                *(float4*)&br[j*4] = *(const float4*)&Bs[kk][tcol*TN + j*4];
            #pragma unroll
            for (int i = 0; i < TM; i++)
                #pragma unroll
                for (int j = 0; j < TN; j++)
                    acc[i][j] += ar[i] * br[j];
        }
        __syncthreads();
    }

    float bv[TN];
    #pragma unroll
    for (int j = 0; j < TN; j++)
        bv[j] = bias ? bias[n0 + tcol*TN + j] : 0.f;

    #pragma unroll
    for (int i = 0; i < TM; i++) {
        const long m = m0 + trow*TM + i;
        #pragma unroll
        for (int j = 0; j < TN; j++) {
            const int n = n0 + tcol*TN + j;
            float v = acc[i][j] * alpha + bv[j];
            if (RELU) v = fmaxf(v, 0.f);
            C[m*ldc + n] = v;
        }
    }
}

// ---------------------------------------------------------------------------
// Row softmax in-place over [rows, 2048]; one block (256 thr) per row.
// ---------------------------------------------------------------------------
__global__ void softmax_k(float* __restrict__ attn)
{
    const long row = blockIdx.x;
    float4* p = (float4*)(attn + row * (long)SS);
    const int t = threadIdx.x;

    float4 a = p[t];
    float4 b = p[t + 256];

    __shared__ float red[256];
    float m = fmaxf(fmaxf(fmaxf(a.x, a.y), fmaxf(a.z, a.w)),
                    fmaxf(fmaxf(b.x, b.y), fmaxf(b.z, b.w)));
    red[t] = m; __syncthreads();
    for (int s = 128; s > 0; s >>= 1) {
        if (t < s) red[t] = fmaxf(red[t], red[t + s]);
        __syncthreads();
    }
    const float mx = red[0]; __syncthreads();

    a.x = expf(a.x - mx); a.y = expf(a.y - mx);
    a.z = expf(a.z - mx); a.w = expf(a.w - mx);
    b.x = expf(b.x - mx); b.y = expf(b.y - mx);
    b.z = expf(b.z - mx); b.w = expf(b.w - mx);

    red[t] = a.x + a.y + a.z + a.w + b.x + b.y + b.z + b.w;
    __syncthreads();
    for (int s = 128; s > 0; s >>= 1) {
        if (t < s) red[t] += red[t + s];
        __syncthreads();
    }
    const float inv = 1.f / red[0];

    a.x *= inv; a.y *= inv; a.z *= inv; a.w *= inv;
    b.x *= inv; b.y *= inv; b.z *= inv; b.w *= inv;
    p[t] = a; p[t + 256] = b;
}

// ---------------------------------------------------------------------------
// out = LayerNorm(a + r) * gamma + beta; one block (256 thr) per token row.
// ---------------------------------------------------------------------------
__global__ void add_ln_k(const float* __restrict__ a, const float* __restrict__ r,
                         const float* __restrict__ g, const float* __restrict__ be,
                         float* __restrict__ o)
{
    const long row = blockIdx.x;
    const int t = threadIdx.x;
    float4 x = ((const float4*)(a + row*DM))[t];
    float4 y = ((const float4*)(r + row*DM))[t];
    x.x += y.x; x.y += y.y; x.z += y.z; x.w += y.w;

    __shared__ float rs[256], rq[256];
    rs[t] = x.x + x.y + x.z + x.w;
    rq[t] = x.x*x.x + x.y*x.y + x.z*x.z + x.w*x.w;
    __syncthreads();
    for (int s = 128; s > 0; s >>= 1) {
        if (t < s) { rs[t] += rs[t + s]; rq[t] += rq[t + s]; }
        __syncthreads();
    }
    const float mu  = rs[0] * (1.f/DM);
    const float var = rq[0] * (1.f/DM) - mu*mu;
    const float rst = rsqrtf(var + 1e-5f);

    float4 gg = ((const float4*)g)[t];
    float4 bb = ((const float4*)be)[t];
    float4 out;
    out.x = (x.x - mu)*rst*gg.x + bb.x;
    out.y = (x.y - mu)*rst*gg.y + bb.y;
    out.z = (x.z - mu)*rst*gg.z + bb.z;
    out.w = (x.w - mu)*rst*gg.w + bb.w;
    ((float4*)(o + row*DM))[t] = out;
}

// ---------------------------------------------------------------------------

using GemmNN  = void(*)(const float*, const float*, const float*, float*,
                        int,int,int,int,int,int,long,long,long,long,long,long,float);

extern "C" void kernel_launch(void* const* d_in, const int* in_sizes, int n_in,
                              void* d_out, int out_size)
{
    const float* src = (const float*)d_in[0];
    const float* wq  = (const float*)d_in[1];
    const float* bq  = (const float*)d_in[2];
    const float* wk  = (const float*)d_in[3];
    const float* bk  = (const float*)d_in[4];
    const float* wv  = (const float*)d_in[5];
    const float* bv  = (const float*)d_in[6];
    const float* wo  = (const float*)d_in[7];
    const float* bo  = (const float*)d_in[8];
    const float* w1  = (const float*)d_in[9];
    const float* b1  = (const float*)d_in[10];
    const float* w2  = (const float*)d_in[11];
    const float* b2  = (const float*)d_in[12];
    const float* g1  = (const float*)d_in[13];
    const float* be1 = (const float*)d_in[14];
    const float* g2  = (const float*)d_in[15];
    const float* be2 = (const float*)d_in[16];

    float* outp  = (float*)d_out;                 // [B,S,D]
    float* attnp = (float*)d_out + OUT_ELEMS;     // [B,H,S,S]

    float *q, *k, *v, *ctx, *t0, *x1, *ff;
    cudaGetSymbolAddress((void**)&q,   g_q);
    cudaGetSymbolAddress((void**)&k,   g_k);
    cudaGetSymbolAddress((void**)&v,   g_v);
    cudaGetSymbolAddress((void**)&ctx, g_ctx);
    cudaGetSymbolAddress((void**)&t0,  g_t0);
    cudaGetSymbolAddress((void**)&x1,  g_x1);
    cudaGetSymbolAddress((void**)&ff,  g_ff);

    const dim3 thr(256);

    // 1-3) QKV projections: [4096,1024] = [4096,1024] @ [1024,1024] + b
    {
        dim3 grid(DM/128, NTOK/128, 1);
        gemm_k<128,128,16,8,8,false,false><<<grid, thr>>>(
            src, wq, bq, q, NTOK, DM, DM, DM, DM, DM, 0,0,0,0,0,0, 1.f);
        gemm_k<128,128,16,8,8,false,false><<<grid, thr>>>(
            src, wk, bk, k, NTOK, DM, DM, DM, DM, DM, 0,0,0,0,0,0, 1.f);
        gemm_k<128,128,16,8,8,false,false><<<grid, thr>>>(
            src, wv, bv, v, NTOK, DM, DM, DM, DM, DM, 0,0,0,0,0,0, 1.f);
    }

    // 4) scores[b,h] = (Q_bh @ K_bh^T) / 8   (written straight into attn output)
    {
        dim3 grid(SS/128, SS/128, BB*NH);
        gemm_k<128,128,16,8,8,true,false><<<grid, thr>>>(
            q, k, nullptr, attnp,
            SS, SS, DK, DM, DM, SS,
            (long)SS*DM, DK,                 // A offsets: b-stride, h-stride
            (long)SS*DM, DK,                 // B offsets
            (long)NH*SS*SS, (long)SS*SS,     // C offsets
            0.125f);
    }

    // 5) row softmax in-place
    softmax_k<<<BB*NH*SS, thr>>>(attnp);

    // 6) ctx[b,h] = P_bh @ V_bh  -> g_ctx laid out as [B,S,H,dk] = [4096,1024]
    {
        dim3 grid(DK/64, SS/128, BB*NH);
        gemm_k<128,64,16,8,4,false,false><<<grid, thr>>>(
            attnp, v, nullptr, ctx,
            SS, DK, SS, SS, DM, DM,
            (long)NH*SS*SS, (long)SS*SS,
            (long)SS*DM, DK,
            (long)SS*DM, DK,
            1.f);
    }

    // 7) attn_out = ctx @ Wo + bo
    {
        dim3 grid(DM/128, NTOK/128, 1);
        gemm_k<128,128,16,8,8,false,false><<<grid, thr>>>(
            ctx, wo, bo, t0, NTOK, DM, DM, DM, DM, DM, 0,0,0,0,0,0, 1.f);
    }

    // 8) x1 = LN(src + attn_out)
    add_ln_k<<<NTOK, thr>>>(src, t0, g1, be1, x1);

    // 9) ff = relu(x1 @ W1 + b1)   [4096,4096]
    {
        dim3 grid(DFF/128, NTOK/128, 1);
        gemm_k<128,128,16,8,8,false,true><<<grid, thr>>>(
            x1, w1, b1, ff, NTOK, DFF, DM, DM, DFF, DFF, 0,0,0,0,0,0, 1.f);
    }

    // 10) t0 = ff @ W2 + b2
    {
        dim3 grid(DM/128, NTOK/128, 1);
        gemm_k<128,128,16,8,8,false,false><<<grid, thr>>>(
            ff, w2, b2, t0, NTOK, DM, DFF, DFF, DM, DM, 0,0,0,0,0,0, 1.f);
    }

    // 11) out = LN(x1 + t0)
    add_ln_k<<<NTOK, thr>>>(x1, t0, g2, be2, outp);
}

// round 3
// speedup vs baseline: 2.6132x; 2.6132x over previous
#include <cuda_runtime.h>
#include <cstdint>

// ---------------- problem constants ----------------
#define BBATCH 2
#define SS 2048
#define DM 1024
#define NH 16
#define DK 64
#define DFF 4096
#define NTOK (BBATCH*SS)                  // 4096
#define OUT_ELEMS ((long)NTOK*DM)         // 4,194,304

// ---------------- scratch (device globals, allocation-free) ----------------
__device__ float g_q  [NTOK*DM];
__device__ float g_k  [NTOK*DM];
__device__ float g_v  [NTOK*DM];
__device__ float g_vt [NTOK*DM];   // V transposed per batch: [B][DM][S]
__device__ float g_ctx[NTOK*DM];
__device__ float g_t0 [NTOK*DM];
__device__ float g_x1 [NTOK*DM];
__device__ float g_ff [NTOK*DFF];
__device__ float g_wqT[DM*DM];
__device__ float g_wkT[DM*DM];
__device__ float g_wvT[DM*DM];
__device__ float g_woT[DM*DM];
__device__ float g_w1T[DM*DFF];
__device__ float g_w2T[DM*DFF];

__device__ __forceinline__ uint32_t tf32r(float x){
    uint32_t r; asm("cvt.rna.tf32.f32 %0, %1;" : "=r"(r) : "f"(x)); return r;
}

// ---------------------------------------------------------------------------
// tf32 mma.sync GEMM: C[M,N] = alpha * A[M,K] * B[N,K]^T + bias (+ReLU)
// A,B K-major fp32 in gmem (rounded to tf32 at smem fill).
// CTA tile 128 x BN, 4 warps (2x2), warp tile 64 x (BN/2), BK=16.
// Batched via blockIdx.z (zb=z>>4, zh=z&15) strides.
// ---------------------------------------------------------------------------
template<int BN>
__global__ void __launch_bounds__(128)
tc_gemm(const float* __restrict__ A, const float* __restrict__ B,
        const float* __restrict__ bias, float* __restrict__ C,
        int K, int lda, int ldb, int ldc,
        long sA_b, long sA_h, long sB_b, long sB_h, long sC_b, long sC_h,
        float alpha, int relu)
{
    constexpr int BK  = 16;
    constexpr int LDSP = 20;            // row pitch (floats): 20 ≡ 4 (mod 32) -> conflict-free frags
    constexpr int WN  = BN/2;           // 64 or 32
    constexpr int NT  = WN/8;           // n-tiles per warp: 8 or 4
    constexpr int AIT = 4;              // 128 rows * 4 segs / 128 thr
    constexpr int BIT = BN/32;          // BN rows * 4 segs / 128 thr

    extern __shared__ float sm[];
    float* AsBase = sm;                     // [2][128*LDSP]
    float* BsBase = sm + 2*128*LDSP;        // [2][BN*LDSP]

    const int tid = threadIdx.x, wid = tid>>5, lane = tid&31;
    { int z = blockIdx.z, zb = z>>4, zh = z&15;
      A += zb*sA_b + zh*sA_h; B += zb*sB_b + zh*sB_h; C += zb*sC_b + zh*sC_h; }
    const int m0 = blockIdx.y*128, n0 = blockIdx.x*BN;
    A += (long)m0*lda;
    B += (long)n0*ldb;

    const int wm = (wid>>1)*64, wn = (wid&1)*WN;
    const int r4 = lane>>2, c4 = lane&3;

    float acc[4][NT][4];
    #pragma unroll
    for (int i = 0; i < 4; i++)
        #pragma unroll
        for (int j = 0; j < NT; j++)
            #pragma unroll
            for (int q = 0; q < 4; q++) acc[i][j][q] = 0.f;

    const int nch = K / BK;
    float4 ra[AIT], rb[BIT];

    // ---- prefetch chunk 0 ----
    #pragma unroll
    for (int i = 0; i < AIT; i++){
        int idx = i*128 + tid;
        ra[i] = *(const float4*)(A + (long)(idx>>2)*lda + (idx&3)*4);
    }
    #pragma unroll
    for (int i = 0; i < BIT; i++){
        int idx = i*128 + tid;
        rb[i] = *(const float4*)(B + (long)(idx>>2)*ldb + (idx&3)*4);
    }
    {
        float* as = AsBase; float* bs = BsBase;
        #pragma unroll
        for (int i = 0; i < AIT; i++){
            int idx = i*128 + tid;
            uint32_t* d = (uint32_t*)(as + (idx>>2)*LDSP + (idx&3)*4);
            d[0]=tf32r(ra[i].x); d[1]=tf32r(ra[i].y); d[2]=tf32r(ra[i].z); d[3]=tf32r(ra[i].w);
        }
        #pragma unroll
        for (int i = 0; i < BIT; i++){
            int idx = i*128 + tid;
            uint32_t* d = (uint32_t*)(bs + (idx>>2)*LDSP + (idx&3)*4);
            d[0]=tf32r(rb[i].x); d[1]=tf32r(rb[i].y); d[2]=tf32r(rb[i].z); d[3]=tf32r(rb[i].w);
        }
    }
    __syncthreads();

    for (int c = 0; c < nch; c++){
        const int st = c & 1;
        if (c+1 < nch){
            const int k0 = (c+1)*BK;
            #pragma unroll
            for (int i = 0; i < AIT; i++){
                int idx = i*128 + tid;
                ra[i] = *(const float4*)(A + (long)(idx>>2)*lda + k0 + (idx&3)*4);
            }
            #pragma unroll
            for (int i = 0; i < BIT; i++){
                int idx = i*128 + tid;
                rb[i] = *(const float4*)(B + (long)(idx>>2)*ldb + k0 + (idx&3)*4);
            }
        }

        const uint32_t* as = (const uint32_t*)(AsBase + st*128*LDSP);
        const uint32_t* bs = (const uint32_t*)(BsBase + st*BN*LDSP);

        #pragma unroll
        for (int ks = 0; ks < 2; ks++){
            uint32_t bf[NT][2];
            #pragma unroll
            for (int nj = 0; nj < NT; nj++){
                const uint32_t* bp = bs + (wn + nj*8 + r4)*LDSP + ks*8 + c4;
                bf[nj][0] = bp[0];
                bf[nj][1] = bp[4];
            }
            #pragma unroll
            for (int mi = 0; mi < 4; mi++){
                const uint32_t* ap = as + (wm + mi*16 + r4)*LDSP + ks*8 + c4;
                uint32_t a0 = ap[0];
                uint32_t a1 = ap[8*LDSP];
                uint32_t a2 = ap[4];
                uint32_t a3 = ap[8*LDSP + 4];
                #pragma unroll
                for (int nj = 0; nj < NT; nj++){
                    asm("mma.sync.aligned.m16n8k8.row.col.f32.tf32.tf32.f32 "
                        "{%0,%1,%2,%3}, {%4,%5,%6,%7}, {%8,%9}, {%0,%1,%2,%3};"
                        : "+f"(acc[mi][nj][0]), "+f"(acc[mi][nj][1]),
                          "+f"(acc[mi][nj][2]), "+f"(acc[mi][nj][3])
                        : "r"(a0), "r"(a1), "r"(a2), "r"(a3),
                          "r"(bf[nj][0]), "r"(bf[nj][1]));
                }
            }
        }

        if (c+1 < nch){
            const int ns = (c+1)&1;
            float* asw = AsBase + ns*128*LDSP;
            float* bsw = BsBase + ns*BN*LDSP;
            #pragma unroll
            for (int i = 0; i < AIT; i++){
                int idx = i*128 + tid;
                uint32_t* d = (uint32_t*)(asw + (idx>>2)*LDSP + (idx&3)*4);
                d[0]=tf32r(ra[i].x); d[1]=tf32r(ra[i].y); d[2]=tf32r(ra[i].z); d[3]=tf32r(ra[i].w);
            }
            #pragma unroll
            for (int i = 0; i < BIT; i++){
                int idx = i*128 + tid;
                uint32_t* d = (uint32_t*)(bsw + (idx>>2)*LDSP + (idx&3)*4);
                d[0]=tf32r(rb[i].x); d[1]=tf32r(rb[i].y); d[2]=tf32r(rb[i].z); d[3]=tf32r(rb[i].w);
            }
        }
        __syncthreads();
    }

    // ---- epilogue: accumulators already in registers ----
    #pragma unroll
    for (int mi = 0; mi < 4; mi++){
        const int row0 = m0 + wm + mi*16 + r4;
        #pragma unroll
        for (int nj = 0; nj < NT; nj++){
            const int col = n0 + wn + nj*8 + c4*2;
            float b0 = 0.f, b1 = 0.f;
            if (bias){ b0 = __ldg(&bias[col]); b1 = __ldg(&bias[col+1]); }
            float v0 = acc[mi][nj][0]*alpha + b0;
            float v1 = acc[mi][nj][1]*alpha + b1;
            float v2 = acc[mi][nj][2]*alpha + b0;
            float v3 = acc[mi][nj][3]*alpha + b1;
            if (relu){
                v0 = fmaxf(v0,0.f); v1 = fmaxf(v1,0.f);
                v2 = fmaxf(v2,0.f); v3 = fmaxf(v3,0.f);
            }
            float2 p0 = {v0, v1}, p1 = {v2, v3};
            *(float2*)&C[(long)row0*ldc + col]      = p0;
            *(float2*)&C[(long)(row0+8)*ldc + col]  = p1;
        }
    }
}

// ---------------------------------------------------------------------------
// Tiled transpose: out[c*R + r] = in[r*C + c], batched via blockIdx.z.
// ---------------------------------------------------------------------------
__global__ void transpose_k(const float* __restrict__ in, float* __restrict__ out,
                            int R, int C)
{
    __shared__ float t[32][33];
    const long zoff = (long)blockIdx.z * R * C;
    in += zoff; out += zoff;
    const int c0 = blockIdx.x*32, r0 = blockIdx.y*32;
    #pragma unroll
    for (int i = threadIdx.y; i < 32; i += 8)
        t[i][threadIdx.x] = in[(long)(r0+i)*C + c0 + threadIdx.x];
    __syncthreads();
    #pragma unroll
    for (int i = threadIdx.y; i < 32; i += 8)
        out[(long)(c0+i)*R + r0 + threadIdx.x] = t[threadIdx.x][i];
}

// ---------------------------------------------------------------------------
// Row softmax in-place over [rows, 2048]; 256 threads per row.
// ---------------------------------------------------------------------------
__global__ void softmax_k(float* __restrict__ attn)
{
    const long row = blockIdx.x;
    float4* p = (float4*)(attn + row * (long)SS);
    const int t = threadIdx.x;
    float4 a = p[t];
    float4 b = p[t + 256];

    __shared__ float red[256];
    float m = fmaxf(fmaxf(fmaxf(a.x,a.y),fmaxf(a.z,a.w)),
                    fmaxf(fmaxf(b.x,b.y),fmaxf(b.z,b.w)));
    red[t] = m; __syncthreads();
    for (int s = 128; s > 0; s >>= 1){
        if (t < s) red[t] = fmaxf(red[t], red[t+s]);
        __syncthreads();
    }
    const float mx = red[0]; __syncthreads();

    a.x = expf(a.x-mx); a.y = expf(a.y-mx); a.z = expf(a.z-mx); a.w = expf(a.w-mx);
    b.x = expf(b.x-mx); b.y = expf(b.y-mx); b.z = expf(b.z-mx); b.w = expf(b.w-mx);

    red[t] = a.x+a.y+a.z+a.w + b.x+b.y+b.z+b.w; __syncthreads();
    for (int s = 128; s > 0; s >>= 1){
        if (t < s) red[t] += red[t+s];
        __syncthreads();
    }
    const float inv = 1.f / red[0];
    a.x*=inv; a.y*=inv; a.z*=inv; a.w*=inv;
    b.x*=inv; b.y*=inv; b.z*=inv; b.w*=inv;
    p[t] = a; p[t+256] = b;
}

// ---------------------------------------------------------------------------
// out = LayerNorm(a + r)*gamma + beta; 256 threads per token row (D=1024).
// ---------------------------------------------------------------------------
__global__ void add_ln_k(const float* __restrict__ a, const float* __restrict__ r,
                         const float* __restrict__ g, const float* __restrict__ be,
                         float* __restrict__ o)
{
    const long row = blockIdx.x;
    const int t = threadIdx.x;
    float4 x = ((const float4*)(a + row*DM))[t];
    float4 y = ((const float4*)(r + row*DM))[t];
    x.x += y.x; x.y += y.y; x.z += y.z; x.w += y.w;

    __shared__ float rs[256], rq[256];
    rs[t] = x.x+x.y+x.z+x.w;
    rq[t] = x.x*x.x + x.y*x.y + x.z*x.z + x.w*x.w;
    __syncthreads();
    for (int s = 128; s > 0; s >>= 1){
        if (t < s){ rs[t] += rs[t+s]; rq[t] += rq[t+s]; }
        __syncthreads();
    }
    const float mu  = rs[0] * (1.f/DM);
    const float var = rq[0] * (1.f/DM) - mu*mu;
    const float rst = rsqrtf(var + 1e-5f);

    float4 gg = ((const float4*)g)[t];
    float4 bb = ((const float4*)be)[t];
    float4 out;
    out.x = (x.x-mu)*rst*gg.x + bb.x;
    out.y = (x.y-mu)*rst*gg.y + bb.y;
    out.z = (x.z-mu)*rst*gg.z + bb.z;
    out.w = (x.w-mu)*rst*gg.w + bb.w;
    ((float4*)(o + row*DM))[t] = out;
}

// ---------------------------------------------------------------------------

extern "C" void kernel_launch(void* const* d_in, const int* in_sizes, int n_in,
                              void* d_out, int out_size)
{
    const float* src = (const float*)d_in[0];
    const float* wq  = (const float*)d_in[1];
    const float* bq  = (const float*)d_in[2];
    const float* wk  = (const float*)d_in[3];
    const float* bk  = (const float*)d_in[4];
    const float* wv  = (const float*)d_in[5];
    const float* bv  = (const float*)d_in[6];
    const float* wo  = (const float*)d_in[7];
    const float* bo  = (const float*)d_in[8];
    const float* w1  = (const float*)d_in[9];
    const float* b1  = (const float*)d_in[10];
    const float* w2  = (const float*)d_in[11];
    const float* b2  = (const float*)d_in[12];
    const float* g1  = (const float*)d_in[13];
    const float* be1 = (const float*)d_in[14];
    const float* g2  = (const float*)d_in[15];
    const float* be2 = (const float*)d_in[16];

    float* outp  = (float*)d_out;
    float* attnp = (float*)d_out + OUT_ELEMS;

    float *q,*k,*v,*vt,*ctx,*t0,*x1,*ff,*wqT,*wkT,*wvT,*woT,*w1T,*w2T;
    cudaGetSymbolAddress((void**)&q,   g_q);
    cudaGetSymbolAddress((void**)&k,   g_k);
    cudaGetSymbolAddress((void**)&v,   g_v);
    cudaGetSymbolAddress((void**)&vt,  g_vt);
    cudaGetSymbolAddress((void**)&ctx, g_ctx);
    cudaGetSymbolAddress((void**)&t0,  g_t0);
    cudaGetSymbolAddress((void**)&x1,  g_x1);
    cudaGetSymbolAddress((void**)&ff,  g_ff);
    cudaGetSymbolAddress((void**)&wqT, g_wqT);
    cudaGetSymbolAddress((void**)&wkT, g_wkT);
    cudaGetSymbolAddress((void**)&wvT, g_wvT);
    cudaGetSymbolAddress((void**)&woT, g_woT);
    cudaGetSymbolAddress((void**)&w1T, g_w1T);
    cudaGetSymbolAddress((void**)&w2T, g_w2T);

    const int SM128 = (2*128*20 + 2*128*20) * 4;   // 40960
    const int SM64  = (2*128*20 + 2*64*20)  * 4;   // 30720

    // ---- 0) transpose weights to [N,K] K-major ----
    {
        dim3 b(32,8);
        transpose_k<<<dim3(32,32,1),  b>>>(wq, wqT, DM, DM);
        transpose_k<<<dim3(32,32,1),  b>>>(wk, wkT, DM, DM);
        transpose_k<<<dim3(32,32,1),  b>>>(wv, wvT, DM, DM);
        transpose_k<<<dim3(32,32,1),  b>>>(wo, woT, DM, DM);
        transpose_k<<<dim3(128,32,1), b>>>(w1, w1T, DM, DFF);   // -> [4096,1024]
        transpose_k<<<dim3(32,128,1), b>>>(w2, w2T, DFF, DM);   // -> [1024,4096]
    }

    // ---- 1) QKV projections ----
    {
        dim3 grid(DM/128, NTOK/128, 1);
        tc_gemm<128><<<grid,128,SM128>>>(src, wqT, bq, q, DM, DM, DM, DM,
                                         0,0,0,0,0,0, 1.f, 0);
        tc_gemm<128><<<grid,128,SM128>>>(src, wkT, bk, k, DM, DM, DM, DM,
                                         0,0,0,0,0,0, 1.f, 0);
        tc_gemm<128><<<grid,128,SM128>>>(src, wvT, bv, v, DM, DM, DM, DM,
                                         0,0,0,0,0,0, 1.f, 0);
    }

    // ---- 2) scores = Q K^T / 8 -> attn output region ----
    {
        dim3 grid(SS/128, SS/128, BBATCH*NH);
        tc_gemm<128><<<grid,128,SM128>>>(q, k, nullptr, attnp, DK, DM, DM, SS,
                                         (long)SS*DM, DK,
                                         (long)SS*DM, DK,
                                         (long)NH*SS*SS, (long)SS*SS,
                                         0.125f, 0);
    }

    // ---- 3) softmax in-place ----
    softmax_k<<<BBATCH*NH*SS, 256>>>(attnp);

    // ---- 4) V transpose per batch: [S,DM] -> [DM,S] ----
    transpose_k<<<dim3(DM/32, SS/32, BBATCH), dim3(32,8)>>>(v, vt, SS, DM);

    // ---- 5) ctx = P @ V ----
    {
        dim3 grid(1, SS/128, BBATCH*NH);
        tc_gemm<64><<<grid,128,SM64>>>(attnp, vt, nullptr, ctx, SS, SS, SS, DM,
                                       (long)NH*SS*SS, (long)SS*SS,
                                       (long)DM*SS, (long)DK*SS,
                                       (long)SS*DM, DK,
                                       1.f, 0);
    }

    // ---- 6) attn_out = ctx @ Wo + bo ----
    {
        dim3 grid(DM/128, NTOK/128, 1);
        tc_gemm<128><<<grid,128,SM128>>>(ctx, woT, bo, t0, DM, DM, DM, DM,
                                         0,0,0,0,0,0, 1.f, 0);
    }

    // ---- 7) x1 = LN(src + attn_out) ----
    add_ln_k<<<NTOK, 256>>>(src, t0, g1, be1, x1);

    // ---- 8) ff = relu(x1 @ W1 + b1) ----
    {
        dim3 grid(DFF/128, NTOK/128, 1);
        tc_gemm<128><<<grid,128,SM128>>>(x1, w1T, b1, ff, DM, DM, DM, DFF,
                                         0,0,0,0,0,0, 1.f, 1);
    }

    // ---- 9) t0 = ff @ W2 + b2 ----
    {
        dim3 grid(DM/128, NTOK/128, 1);
        tc_gemm<128><<<grid,128,SM128>>>(ff, w2T, b2, t0, DFF, DFF, DFF, DM,
                                         0,0,0,0,0,0, 1.f, 0);
    }

    // ---- 10) out = LN(x1 + t0) ----
    add_ln_k<<<NTOK, 256>>>(x1, t0, g2, be2, outp);
}